// round 2
// baseline (speedup 1.0000x reference)
#include <cuda_runtime.h>

// Problem constants
#define Nn   10000
#define Bb   4
#define Ff   16
#define Tt   12
#define Ee   160000
#define Cc   64
#define ROW  768          // Bb*Tt*Ff floats per node
#define ROW4 192          // ROW/4 (float4)

typedef unsigned long long u64;

__device__ __forceinline__ u64 ffma2(u64 a, u64 b, u64 c) {
    u64 d;
    asm("fma.rn.f32x2 %0, %1, %2, %3;" : "=l"(d) : "l"(a), "l"(b), "l"(c));
    return d;
}
__device__ __forceinline__ float hsum2(u64 v) {
    float lo, hi;
    asm("mov.b64 {%0, %1}, %2;" : "=f"(lo), "=f"(hi) : "l"(v));
    return lo + hi;
}

// ---------------- scratch (device globals; no allocation) ----------------
__device__ float g_Tx0[Nn * ROW];
__device__ float g_Tx1[Nn * ROW];
__device__ float g_Tx2[Nn * ROW];
__device__ float g_deg[Nn];
__device__ int   g_degin[Nn];
__device__ int   g_off[Nn + 1];
__device__ int   g_cur[Nn];
__device__ int   g_srcs[Ee];

// ---------------- graph preprocessing ----------------
__global__ void k_zero() {
    int i = blockIdx.x * blockDim.x + threadIdx.x;
    if (i < Nn) { g_deg[i] = 0.0f; g_degin[i] = 0; }
}

__global__ void k_count(const int* __restrict__ ei) {
    int e = blockIdx.x * blockDim.x + threadIdx.x;
    if (e < Ee) {
        atomicAdd(&g_deg[ei[e]], 1.0f);       // out-degree by row
        atomicAdd(&g_degin[ei[Ee + e]], 1);   // in-degree by col
    }
}

// single-block exclusive scan over g_degin -> g_off, g_cur
__global__ void k_scan() {
    __shared__ int part[1024];
    int t = threadIdx.x;
    const int CH = 10;                 // 1024*10 >= Nn
    int base = t * CH;
    int local[CH];
    int s = 0;
#pragma unroll
    for (int i = 0; i < CH; i++) {
        int idx = base + i;
        int v = (idx < Nn) ? g_degin[idx] : 0;
        local[i] = v; s += v;
    }
    part[t] = s;
    __syncthreads();
    for (int off = 1; off < 1024; off <<= 1) {
        int v = (t >= off) ? part[t - off] : 0;
        __syncthreads();
        part[t] += v;
        __syncthreads();
    }
    int pre = (t == 0) ? 0 : part[t - 1];
#pragma unroll
    for (int i = 0; i < CH; i++) {
        int idx = base + i;
        if (idx < Nn) { g_off[idx] = pre; g_cur[idx] = pre; pre += local[i]; }
    }
    if (t == 1023) g_off[Nn] = part[1023];
}

__global__ void k_fill(const int* __restrict__ ei) {
    int e = blockIdx.x * blockDim.x + threadIdx.x;
    if (e < Ee) {
        int c = ei[Ee + e];
        int p = atomicAdd(&g_cur[c], 1);
        g_srcs[p] = ei[e];
    }
}

// ---------------- transpose x (B,N,F,T) -> Tx0 (N,B,T,F) ----------------
__global__ void k_transpose(const float* __restrict__ x) {
    int bn = blockIdx.x;               // b*Nn + n
    int b = bn / Nn, n = bn - b * Nn;
    __shared__ float tile[ROW4];
    int tid = threadIdx.x;             // 0..191
    tile[tid] = x[bn * ROW4 + tid];    // (f*12 + t)
    __syncthreads();
    int t = tid >> 4, f = tid & 15;
    g_Tx0[n * ROW + b * ROW4 + tid] = tile[f * Tt + t];  // (t*16 + f)
}

// ---------------- Lhat via CSR gather ----------------
__global__ void k_lhat1(const float* __restrict__ lamp) {
    int n = blockIdx.x, j = threadIdx.x;     // j: float4 index 0..191
    const float4* u = (const float4*)g_Tx0;
    float4 acc = make_float4(0.f, 0.f, 0.f, 0.f);
    int e = g_off[n], e1 = g_off[n + 1];
    for (; e + 4 <= e1; e += 4) {
        int s0 = g_srcs[e], s1 = g_srcs[e + 1], s2 = g_srcs[e + 2], s3 = g_srcs[e + 3];
        float4 v0 = u[s0 * ROW4 + j], v1 = u[s1 * ROW4 + j];
        float4 v2 = u[s2 * ROW4 + j], v3 = u[s3 * ROW4 + j];
        acc.x += (v0.x + v1.x) + (v2.x + v3.x);
        acc.y += (v0.y + v1.y) + (v2.y + v3.y);
        acc.z += (v0.z + v1.z) + (v2.z + v3.z);
        acc.w += (v0.w + v1.w) + (v2.w + v3.w);
    }
    for (; e < e1; e++) {
        float4 v = u[g_srcs[e] * ROW4 + j];
        acc.x += v.x; acc.y += v.y; acc.z += v.z; acc.w += v.w;
    }
    float4 un = u[n * ROW4 + j];
    float c2 = 2.0f / lamp[0];
    float dn = g_deg[n];
    float4 r;
    r.x = c2 * (dn * un.x - acc.x) - un.x;
    r.y = c2 * (dn * un.y - acc.y) - un.y;
    r.z = c2 * (dn * un.z - acc.z) - un.z;
    r.w = c2 * (dn * un.w - acc.w) - un.w;
    ((float4*)g_Tx1)[n * ROW4 + j] = r;
}

__global__ void k_lhat2(const float* __restrict__ lamp) {
    int n = blockIdx.x, j = threadIdx.x;
    const float4* u = (const float4*)g_Tx1;
    float4 acc = make_float4(0.f, 0.f, 0.f, 0.f);
    int e = g_off[n], e1 = g_off[n + 1];
    for (; e + 4 <= e1; e += 4) {
        int s0 = g_srcs[e], s1 = g_srcs[e + 1], s2 = g_srcs[e + 2], s3 = g_srcs[e + 3];
        float4 v0 = u[s0 * ROW4 + j], v1 = u[s1 * ROW4 + j];
        float4 v2 = u[s2 * ROW4 + j], v3 = u[s3 * ROW4 + j];
        acc.x += (v0.x + v1.x) + (v2.x + v3.x);
        acc.y += (v0.y + v1.y) + (v2.y + v3.y);
        acc.z += (v0.z + v1.z) + (v2.z + v3.z);
        acc.w += (v0.w + v1.w) + (v2.w + v3.w);
    }
    for (; e < e1; e++) {
        float4 v = u[g_srcs[e] * ROW4 + j];
        acc.x += v.x; acc.y += v.y; acc.z += v.z; acc.w += v.w;
    }
    float4 un = u[n * ROW4 + j];
    float4 t0 = ((const float4*)g_Tx0)[n * ROW4 + j];
    float c2 = 2.0f / lamp[0];
    float dn = g_deg[n];
    float4 r;
    r.x = 2.0f * (c2 * (dn * un.x - acc.x) - un.x) - t0.x;
    r.y = 2.0f * (c2 * (dn * un.y - acc.y) - un.y) - t0.y;
    r.z = 2.0f * (c2 * (dn * un.z - acc.z) - un.z) - t0.z;
    r.w = 2.0f * (c2 * (dn * un.w - acc.w) - un.w) - t0.w;
    ((float4*)g_Tx2)[n * ROW4 + j] = r;
}

// ---------------- fused cheb-proj + temporal conv + residual + LN ----------------
// Packed f32x2 version: all reductions pack even/odd reduction-index terms
// into lo/hi of a 64-bit packed float2 and use fma.rn.f32x2 (FFMA2).
//
// block = 256 threads = 4 groups of 64; group g handles (n = q, b = g)
// smem layout (floats):
//   wch2 [0,3072)      cheb weights float2-packed over j pairs: u64[jp(24)][c(64)]
//   wt2  [3072,15360)  time weights: u64[d(3)][cip(32)][c(64)]
//   wr2  [15360,16384) res weights:  u64[fp(8)][c(64)]
//   cb/trb/gma/bta [16384,16640)
//   per group (stride 2456, base 16640):
//     tx2  +0    .. 576   u64-packed [jp(24)][t(12)] rows of 24 floats
//     sp2  +576  .. 1472  u64-packed [cip(32)][tpos(14)] rows of 28 floats
//     xr2  +1472 .. 1664  u64-packed [fp(8)][t(12)] rows of 24 floats
//     hs   +1664 .. 2432  [t(12)][c(64)]
//     mu   +2432..2444   rs +2444..2456
#define GB_BASE 16640
#define GB_STRIDE 2456
#define SMEM_FLOATS (GB_BASE + 4 * GB_STRIDE)   // 26464 floats = 105856 B

__global__ void __launch_bounds__(256, 2)
k_fused(const float* __restrict__ x,
        const float* __restrict__ chebW, const float* __restrict__ chebB,
        const float* __restrict__ timeW, const float* __restrict__ timeB,
        const float* __restrict__ resW,  const float* __restrict__ resB,
        const float* __restrict__ gamma, const float* __restrict__ beta,
        float* __restrict__ out)
{
    extern __shared__ float sm[];
    float* cb  = sm + 16384;
    float* trb = sm + 16448;
    float* gma = sm + 16512;
    float* bta = sm + 16576;

    const u64* wchu = (const u64*)(sm);          // [jp*64 + c]
    const u64* wtu  = (const u64*)(sm + 3072);   // [d*2048 + cip*64 + c]
    const u64* wru  = (const u64*)(sm + 15360);  // [fp*64 + c]

    int tid = threadIdx.x;

    // --- one-time weight staging (packed float2 over reduction pairs) ---
    for (int i = tid; i < 1536; i += 256) {          // cheb: jp in [0,24), c in [0,64)
        int jp = i >> 6, c = i & 63;
        sm[2 * i]     = chebW[(2 * jp) * 64 + c];
        sm[2 * i + 1] = chebW[(2 * jp + 1) * 64 + c];
    }
    for (int i = tid; i < 6144; i += 256) {          // time: d(3), cip(32), c(64)
        int d = i >> 11; int r = i & 2047;
        int cip = r >> 6; int c = r & 63;
        sm[3072 + 2 * i]     = timeW[c * 192 + (2 * cip) * 3 + d];
        sm[3072 + 2 * i + 1] = timeW[c * 192 + (2 * cip + 1) * 3 + d];
    }
    for (int i = tid; i < 512; i += 256) {           // res: fp(8), c(64)
        int fp = i >> 6, c = i & 63;
        sm[15360 + 2 * i]     = resW[c * 16 + 2 * fp];
        sm[15360 + 2 * i + 1] = resW[c * 16 + 2 * fp + 1];
    }
    if (tid < 64) {
        cb[tid]  = chebB[tid];
        trb[tid] = timeB[tid] + resB[tid];
        gma[tid] = gamma[tid];
        bta[tid] = beta[tid];
    }

    const int g = tid >> 6;        // group = batch b
    const int c = tid & 63;        // channel
    const int lane = tid & 31;
    const int w01 = (tid >> 5) & 1;

    float* gbase  = sm + GB_BASE + g * GB_STRIDE;
    float* mytx   = gbase;              // 576
    float* myspad = gbase + 576;        // 896
    float* myxr   = gbase + 1472;       // 192
    float* myhs   = gbase + 1664;       // 768
    float* mymu   = gbase + 2432;
    float* myrs   = gbase + 2444;

    // zero spad boundary slots (tpos 0 and 13) once; only [1..12] rewritten
    {
        float* sp = myspad + (c >> 1) * 28 + (c & 1);
        sp[0] = 0.f; sp[26] = 0.f;
    }
    __syncthreads();

    for (int q = blockIdx.x; q < Nn; q += gridDim.x) {
        const int n = q;

        // ---- Stage 0: cooperative loads (global-coalesced, smem interleaved) ----
        for (int i = tid; i < 2304; i += 256) {
            int gg = i / 576; int r = i - gg * 576;
            int k = r / 192;  int rr = r - k * 192;     // rr = t*16+f
            int t = rr >> 4, f = rr & 15;
            const float* src = (k == 0) ? g_Tx0 : (k == 1) ? g_Tx1 : g_Tx2;
            float v = src[n * ROW + gg * ROW4 + rr];
            int j = k * 16 + f;
            sm[GB_BASE + gg * GB_STRIDE + (j >> 1) * 24 + t * 2 + (j & 1)] = v;
        }
        for (int i = tid; i < 768; i += 256) {
            int gg = i / 192; int r = i - gg * 192;
            int f = r / 12, t = r - f * 12;
            float v = x[(gg * Nn + n) * ROW4 + r];
            sm[GB_BASE + gg * GB_STRIDE + 1472 + (f >> 1) * 24 + t * 2 + (f & 1)] = v;
        }
        __syncthreads();

        // ---- Stage A: cheb projection (packed over j-pairs), relu -> spad ----
        {
            u64 acc[12];
#pragma unroll
            for (int t = 0; t < 12; t++) acc[t] = 0ull;
#pragma unroll 4
            for (int jp = 0; jp < 24; jp++) {
                const ulonglong2* row = (const ulonglong2*)(mytx + jp * 24);
                ulonglong2 p0 = row[0], p1 = row[1], p2 = row[2];
                ulonglong2 p3 = row[3], p4 = row[4], p5 = row[5];
                u64 w = wchu[jp * 64 + c];
                acc[0]  = ffma2(p0.x, w, acc[0]);  acc[1]  = ffma2(p0.y, w, acc[1]);
                acc[2]  = ffma2(p1.x, w, acc[2]);  acc[3]  = ffma2(p1.y, w, acc[3]);
                acc[4]  = ffma2(p2.x, w, acc[4]);  acc[5]  = ffma2(p2.y, w, acc[5]);
                acc[6]  = ffma2(p3.x, w, acc[6]);  acc[7]  = ffma2(p3.y, w, acc[7]);
                acc[8]  = ffma2(p4.x, w, acc[8]);  acc[9]  = ffma2(p4.y, w, acc[9]);
                acc[10] = ffma2(p5.x, w, acc[10]); acc[11] = ffma2(p5.y, w, acc[11]);
            }
            float bias = cb[c];
            float* sp = myspad + (c >> 1) * 28 + (c & 1);
#pragma unroll
            for (int t = 0; t < 12; t++)
                sp[(t + 1) * 2] = fmaxf(hsum2(acc[t]) + bias, 0.f);
        }
        __syncthreads();

        // ---- Stage B: temporal conv (packed over ci-pairs) + residual, relu ----
        float h[12];
        {
            u64 acc[12];
#pragma unroll
            for (int t = 0; t < 12; t++) acc[t] = 0ull;
#pragma unroll 2
            for (int cip = 0; cip < 32; cip++) {
                const ulonglong2* row = (const ulonglong2*)(myspad + cip * 28);
                ulonglong2 q0 = row[0], q1 = row[1], q2 = row[2], q3 = row[3];
                ulonglong2 q4 = row[4], q5 = row[5], q6 = row[6];
                u64 s[14] = { q0.x, q0.y, q1.x, q1.y, q2.x, q2.y, q3.x,
                              q3.y, q4.x, q4.y, q5.x, q5.y, q6.x, q6.y };
                u64 w0 = wtu[cip * 64 + c];
                u64 w1 = wtu[2048 + cip * 64 + c];
                u64 w2 = wtu[4096 + cip * 64 + c];
#pragma unroll
                for (int t = 0; t < 12; t++) {
                    acc[t] = ffma2(s[t],     w0, acc[t]);
                    acc[t] = ffma2(s[t + 1], w1, acc[t]);
                    acc[t] = ffma2(s[t + 2], w2, acc[t]);
                }
            }
#pragma unroll
            for (int fp = 0; fp < 8; fp++) {
                const ulonglong2* row = (const ulonglong2*)(myxr + fp * 24);
                ulonglong2 p0 = row[0], p1 = row[1], p2 = row[2];
                ulonglong2 p3 = row[3], p4 = row[4], p5 = row[5];
                u64 v[12] = { p0.x, p0.y, p1.x, p1.y, p2.x, p2.y,
                              p3.x, p3.y, p4.x, p4.y, p5.x, p5.y };
                u64 w = wru[fp * 64 + c];
#pragma unroll
                for (int t = 0; t < 12; t++) acc[t] = ffma2(v[t], w, acc[t]);
            }
            float bb = trb[c];
#pragma unroll
            for (int t = 0; t < 12; t++) {
                h[t] = fmaxf(hsum2(acc[t]) + bb, 0.f);
                myhs[t * 64 + c] = h[t];
            }
        }
        __syncthreads();

        // ---- LN stats: each of the group's 2 warps reduces 6 t-rows ----
        {
#pragma unroll
            for (int r = 0; r < 6; r++) {
                int t = w01 * 6 + r;
                float v1 = myhs[t * 64 + lane];
                float v2 = myhs[t * 64 + 32 + lane];
                float s = v1 + v2;
                float sq = v1 * v1 + v2 * v2;
#pragma unroll
                for (int o = 16; o > 0; o >>= 1) {
                    s  += __shfl_xor_sync(0xffffffffu, s, o);
                    sq += __shfl_xor_sync(0xffffffffu, sq, o);
                }
                if (lane == 0) {
                    float mu = s * (1.0f / 64.0f);
                    float var = sq * (1.0f / 64.0f) - mu * mu;
                    mymu[t] = mu;
                    myrs[t] = rsqrtf(var + 1e-5f);
                }
            }
        }
        __syncthreads();

        // ---- normalize + write out (B,N,C,T), coalesced float4 ----
        {
            float ga = gma[c], be = bta[c];
            float o[12];
#pragma unroll
            for (int t = 0; t < 12; t++)
                o[t] = (h[t] - mymu[t]) * myrs[t] * ga + be;
            float* op = out + (((size_t)g * Nn + n) * 64 + c) * 12;
            float4* op4 = (float4*)op;
            op4[0] = make_float4(o[0], o[1], o[2],  o[3]);
            op4[1] = make_float4(o[4], o[5], o[6],  o[7]);
            op4[2] = make_float4(o[8], o[9], o[10], o[11]);
        }
        __syncthreads();
    }
}

// ---------------- launcher ----------------
extern "C" void kernel_launch(void* const* d_in, const int* in_sizes, int n_in,
                              void* d_out, int out_size)
{
    const float* x     = (const float*)d_in[0];
    const int*   ei    = (const int*)d_in[1];
    const float* lam   = (const float*)d_in[2];
    const float* chebW = (const float*)d_in[3];
    const float* chebB = (const float*)d_in[4];
    const float* timeW = (const float*)d_in[5];
    const float* timeB = (const float*)d_in[6];
    const float* resW  = (const float*)d_in[7];
    const float* resB  = (const float*)d_in[8];
    const float* gma   = (const float*)d_in[9];
    const float* bta   = (const float*)d_in[10];
    float* out = (float*)d_out;

    k_zero<<<(Nn + 255) / 256, 256>>>();
    k_count<<<(Ee + 255) / 256, 256>>>(ei);
    k_scan<<<1, 1024>>>();
    k_fill<<<(Ee + 255) / 256, 256>>>(ei);
    k_transpose<<<Bb * Nn, 192>>>(x);
    k_lhat1<<<Nn, 192>>>(lam);
    k_lhat2<<<Nn, 192>>>(lam);

    cudaFuncSetAttribute(k_fused, cudaFuncAttributeMaxDynamicSharedMemorySize,
                         SMEM_FLOATS * 4);
    k_fused<<<2960, 256, SMEM_FLOATS * 4>>>(x, chebW, chebB, timeW, timeB,
                                            resW, resB, gma, bta, out);
}

// round 3
// speedup vs baseline: 1.7365x; 1.7365x over previous
#include <cuda_runtime.h>

// Problem constants
#define Nn   10000
#define Bb   4
#define Ff   16
#define Tt   12
#define Ee   160000
#define Cc   64
#define ROW  768          // Bb*Tt*Ff floats per node
#define ROW4 192          // ROW/4 (float4)

typedef unsigned long long u64;

__device__ __forceinline__ u64 ffma2(u64 a, u64 b, u64 c) {
    u64 d;
    asm("fma.rn.f32x2 %0, %1, %2, %3;" : "=l"(d) : "l"(a), "l"(b), "l"(c));
    return d;
}
__device__ __forceinline__ float hsum2(u64 v) {
    float lo, hi;
    asm("mov.b64 {%0, %1}, %2;" : "=f"(lo), "=f"(hi) : "l"(v));
    return lo + hi;
}

// ---------------- scratch (device globals; no allocation) ----------------
__device__ float g_Tx0[Nn * ROW];
__device__ float g_Tx1[Nn * ROW];
__device__ float g_Tx2[Nn * ROW];
__device__ float g_deg[Nn];
__device__ int   g_degin[Nn];
__device__ int   g_off[Nn + 1];
__device__ int   g_cur[Nn];
__device__ int   g_srcs[Ee];

// ---------------- graph preprocessing ----------------
__global__ void k_zero() {
    int i = blockIdx.x * blockDim.x + threadIdx.x;
    if (i < Nn) { g_deg[i] = 0.0f; g_degin[i] = 0; }
}

__global__ void k_count(const int* __restrict__ ei) {
    int e = blockIdx.x * blockDim.x + threadIdx.x;
    if (e < Ee) {
        atomicAdd(&g_deg[ei[e]], 1.0f);       // out-degree by row
        atomicAdd(&g_degin[ei[Ee + e]], 1);   // in-degree by col
    }
}

// single-block exclusive scan over g_degin -> g_off, g_cur
__global__ void k_scan() {
    __shared__ int part[1024];
    int t = threadIdx.x;
    const int CH = 10;                 // 1024*10 >= Nn
    int base = t * CH;
    int local[CH];
    int s = 0;
#pragma unroll
    for (int i = 0; i < CH; i++) {
        int idx = base + i;
        int v = (idx < Nn) ? g_degin[idx] : 0;
        local[i] = v; s += v;
    }
    part[t] = s;
    __syncthreads();
    for (int off = 1; off < 1024; off <<= 1) {
        int v = (t >= off) ? part[t - off] : 0;
        __syncthreads();
        part[t] += v;
        __syncthreads();
    }
    int pre = (t == 0) ? 0 : part[t - 1];
#pragma unroll
    for (int i = 0; i < CH; i++) {
        int idx = base + i;
        if (idx < Nn) { g_off[idx] = pre; g_cur[idx] = pre; pre += local[i]; }
    }
    if (t == 1023) g_off[Nn] = part[1023];
}

__global__ void k_fill(const int* __restrict__ ei) {
    int e = blockIdx.x * blockDim.x + threadIdx.x;
    if (e < Ee) {
        int c = ei[Ee + e];
        int p = atomicAdd(&g_cur[c], 1);
        g_srcs[p] = ei[e];
    }
}

// ---------------- transpose x (B,N,F,T) -> Tx0 (N,B,T,F) ----------------
__global__ void k_transpose(const float* __restrict__ x) {
    int bn = blockIdx.x;               // b*Nn + n
    int b = bn / Nn, n = bn - b * Nn;
    __shared__ float tile[ROW4];
    int tid = threadIdx.x;             // 0..191
    tile[tid] = x[bn * ROW4 + tid];    // (f*12 + t)
    __syncthreads();
    int t = tid >> 4, f = tid & 15;
    g_Tx0[n * ROW + b * ROW4 + tid] = tile[f * Tt + t];  // (t*16 + f)
}

// ---------------- Lhat via CSR gather ----------------
__global__ void k_lhat1(const float* __restrict__ lamp) {
    int n = blockIdx.x, j = threadIdx.x;     // j: float4 index 0..191
    const float4* u = (const float4*)g_Tx0;
    float4 acc = make_float4(0.f, 0.f, 0.f, 0.f);
    int e = g_off[n], e1 = g_off[n + 1];
    for (; e + 4 <= e1; e += 4) {
        int s0 = g_srcs[e], s1 = g_srcs[e + 1], s2 = g_srcs[e + 2], s3 = g_srcs[e + 3];
        float4 v0 = u[s0 * ROW4 + j], v1 = u[s1 * ROW4 + j];
        float4 v2 = u[s2 * ROW4 + j], v3 = u[s3 * ROW4 + j];
        acc.x += (v0.x + v1.x) + (v2.x + v3.x);
        acc.y += (v0.y + v1.y) + (v2.y + v3.y);
        acc.z += (v0.z + v1.z) + (v2.z + v3.z);
        acc.w += (v0.w + v1.w) + (v2.w + v3.w);
    }
    for (; e < e1; e++) {
        float4 v = u[g_srcs[e] * ROW4 + j];
        acc.x += v.x; acc.y += v.y; acc.z += v.z; acc.w += v.w;
    }
    float4 un = u[n * ROW4 + j];
    float c2 = 2.0f / lamp[0];
    float dn = g_deg[n];
    float4 r;
    r.x = c2 * (dn * un.x - acc.x) - un.x;
    r.y = c2 * (dn * un.y - acc.y) - un.y;
    r.z = c2 * (dn * un.z - acc.z) - un.z;
    r.w = c2 * (dn * un.w - acc.w) - un.w;
    ((float4*)g_Tx1)[n * ROW4 + j] = r;
}

__global__ void k_lhat2(const float* __restrict__ lamp) {
    int n = blockIdx.x, j = threadIdx.x;
    const float4* u = (const float4*)g_Tx1;
    float4 acc = make_float4(0.f, 0.f, 0.f, 0.f);
    int e = g_off[n], e1 = g_off[n + 1];
    for (; e + 4 <= e1; e += 4) {
        int s0 = g_srcs[e], s1 = g_srcs[e + 1], s2 = g_srcs[e + 2], s3 = g_srcs[e + 3];
        float4 v0 = u[s0 * ROW4 + j], v1 = u[s1 * ROW4 + j];
        float4 v2 = u[s2 * ROW4 + j], v3 = u[s3 * ROW4 + j];
        acc.x += (v0.x + v1.x) + (v2.x + v3.x);
        acc.y += (v0.y + v1.y) + (v2.y + v3.y);
        acc.z += (v0.z + v1.z) + (v2.z + v3.z);
        acc.w += (v0.w + v1.w) + (v2.w + v3.w);
    }
    for (; e < e1; e++) {
        float4 v = u[g_srcs[e] * ROW4 + j];
        acc.x += v.x; acc.y += v.y; acc.z += v.z; acc.w += v.w;
    }
    float4 un = u[n * ROW4 + j];
    float4 t0 = ((const float4*)g_Tx0)[n * ROW4 + j];
    float c2 = 2.0f / lamp[0];
    float dn = g_deg[n];
    float4 r;
    r.x = 2.0f * (c2 * (dn * un.x - acc.x) - un.x) - t0.x;
    r.y = 2.0f * (c2 * (dn * un.y - acc.y) - un.y) - t0.y;
    r.z = 2.0f * (c2 * (dn * un.z - acc.z) - un.z) - t0.z;
    r.w = 2.0f * (c2 * (dn * un.w - acc.w) - un.w) - t0.w;
    ((float4*)g_Tx2)[n * ROW4 + j] = r;
}

// ---------------- fused cheb-proj + temporal conv + residual + LN ----------------
// Packed f32x2 (even/odd reduction-index in lo/hi), register-pressure capped:
// Stage B runs two 6-t half-passes so the live set stays ~70 regs (no spills).
#define GB_BASE 16640
#define GB_STRIDE 2456
#define SMEM_FLOATS (GB_BASE + 4 * GB_STRIDE)   // 26464 floats = 105856 B

__global__ void __launch_bounds__(256, 2)
k_fused(const float* __restrict__ x,
        const float* __restrict__ chebW, const float* __restrict__ chebB,
        const float* __restrict__ timeW, const float* __restrict__ timeB,
        const float* __restrict__ resW,  const float* __restrict__ resB,
        const float* __restrict__ gamma, const float* __restrict__ beta,
        float* __restrict__ out)
{
    extern __shared__ float sm[];
    float* cb  = sm + 16384;
    float* trb = sm + 16448;
    float* gma = sm + 16512;
    float* bta = sm + 16576;

    const u64* wchu = (const u64*)(sm);          // [jp*64 + c]
    const u64* wtu  = (const u64*)(sm + 3072);   // [d*2048 + cip*64 + c]
    const u64* wru  = (const u64*)(sm + 15360);  // [fp*64 + c]

    int tid = threadIdx.x;

    // --- one-time weight staging (packed float2 over reduction pairs) ---
    for (int i = tid; i < 1536; i += 256) {          // cheb: jp in [0,24), c in [0,64)
        int jp = i >> 6, c = i & 63;
        sm[2 * i]     = chebW[(2 * jp) * 64 + c];
        sm[2 * i + 1] = chebW[(2 * jp + 1) * 64 + c];
    }
    for (int i = tid; i < 6144; i += 256) {          // time: d(3), cip(32), c(64)
        int d = i >> 11; int r = i & 2047;
        int cip = r >> 6; int c = r & 63;
        sm[3072 + 2 * i]     = timeW[c * 192 + (2 * cip) * 3 + d];
        sm[3072 + 2 * i + 1] = timeW[c * 192 + (2 * cip + 1) * 3 + d];
    }
    for (int i = tid; i < 512; i += 256) {           // res: fp(8), c(64)
        int fp = i >> 6, c = i & 63;
        sm[15360 + 2 * i]     = resW[c * 16 + 2 * fp];
        sm[15360 + 2 * i + 1] = resW[c * 16 + 2 * fp + 1];
    }
    if (tid < 64) {
        cb[tid]  = chebB[tid];
        trb[tid] = timeB[tid] + resB[tid];
        gma[tid] = gamma[tid];
        bta[tid] = beta[tid];
    }

    const int g = tid >> 6;        // group = batch b
    const int c = tid & 63;        // channel
    const int lane = tid & 31;
    const int w01 = (tid >> 5) & 1;

    float* gbase  = sm + GB_BASE + g * GB_STRIDE;
    float* mytx   = gbase;              // 576: u64[jp(24)][t(12)]
    float* myspad = gbase + 576;        // 896: u64[cip(32)][tpos(14)]
    float* myxr   = gbase + 1472;       // 192: u64[fp(8)][t(12)]
    float* myhs   = gbase + 1664;       // 768: [t(12)][c(64)]
    float* mymu   = gbase + 2432;
    float* myrs   = gbase + 2444;

    // zero spad boundary slots (tpos 0 and 13) once; only [1..12] rewritten
    {
        float* sp = myspad + (c >> 1) * 28 + (c & 1);
        sp[0] = 0.f; sp[26] = 0.f;
    }
    __syncthreads();

    for (int q = blockIdx.x; q < Nn; q += gridDim.x) {
        const int n = q;

        // ---- Stage 0: cooperative loads (global-coalesced, smem interleaved) ----
        for (int i = tid; i < 2304; i += 256) {
            int gg = i / 576; int r = i - gg * 576;
            int k = r / 192;  int rr = r - k * 192;     // rr = t*16+f
            int t = rr >> 4, f = rr & 15;
            const float* src = (k == 0) ? g_Tx0 : (k == 1) ? g_Tx1 : g_Tx2;
            float v = src[n * ROW + gg * ROW4 + rr];
            int j = k * 16 + f;
            sm[GB_BASE + gg * GB_STRIDE + (j >> 1) * 24 + t * 2 + (j & 1)] = v;
        }
        for (int i = tid; i < 768; i += 256) {
            int gg = i / 192; int r = i - gg * 192;
            int f = r / 12, t = r - f * 12;
            float v = x[(gg * Nn + n) * ROW4 + r];
            sm[GB_BASE + gg * GB_STRIDE + 1472 + (f >> 1) * 24 + t * 2 + (f & 1)] = v;
        }
        __syncthreads();

        // ---- Stage A: cheb projection (packed over j-pairs), relu -> spad ----
        {
            u64 acc[12];
#pragma unroll
            for (int t = 0; t < 12; t++) acc[t] = 0ull;
#pragma unroll 2
            for (int jp = 0; jp < 24; jp++) {
                const ulonglong2* row = (const ulonglong2*)(mytx + jp * 24);
                ulonglong2 p0 = row[0], p1 = row[1], p2 = row[2];
                ulonglong2 p3 = row[3], p4 = row[4], p5 = row[5];
                u64 w = wchu[jp * 64 + c];
                acc[0]  = ffma2(p0.x, w, acc[0]);  acc[1]  = ffma2(p0.y, w, acc[1]);
                acc[2]  = ffma2(p1.x, w, acc[2]);  acc[3]  = ffma2(p1.y, w, acc[3]);
                acc[4]  = ffma2(p2.x, w, acc[4]);  acc[5]  = ffma2(p2.y, w, acc[5]);
                acc[6]  = ffma2(p3.x, w, acc[6]);  acc[7]  = ffma2(p3.y, w, acc[7]);
                acc[8]  = ffma2(p4.x, w, acc[8]);  acc[9]  = ffma2(p4.y, w, acc[9]);
                acc[10] = ffma2(p5.x, w, acc[10]); acc[11] = ffma2(p5.y, w, acc[11]);
            }
            float bias = cb[c];
            float* sp = myspad + (c >> 1) * 28 + (c & 1);
#pragma unroll
            for (int t = 0; t < 12; t++)
                sp[(t + 1) * 2] = fmaxf(hsum2(acc[t]) + bias, 0.f);
        }
        __syncthreads();

        // ---- Stage B: temporal conv + residual in two 6-t half-passes ----
        float h[12];
        {
            float bb = trb[c];
#pragma unroll
            for (int half = 0; half < 2; half++) {
                u64 acc[6];
#pragma unroll
                for (int tt = 0; tt < 6; tt++) acc[tt] = 0ull;
#pragma unroll 1
                for (int cip = 0; cip < 32; cip++) {
                    const ulonglong2* row =
                        (const ulonglong2*)(myspad + cip * 28 + 12 * half);
                    ulonglong2 q0 = row[0], q1 = row[1], q2 = row[2], q3 = row[3];
                    u64 w0 = wtu[cip * 64 + c];
                    u64 w1 = wtu[2048 + cip * 64 + c];
                    u64 w2 = wtu[4096 + cip * 64 + c];
                    // local slots s[0..7] = q0.x,q0.y,q1.x,q1.y,q2.x,q2.y,q3.x,q3.y
                    acc[0] = ffma2(q0.x, w0, acc[0]);
                    acc[0] = ffma2(q0.y, w1, acc[0]);
                    acc[0] = ffma2(q1.x, w2, acc[0]);
                    acc[1] = ffma2(q0.y, w0, acc[1]);
                    acc[1] = ffma2(q1.x, w1, acc[1]);
                    acc[1] = ffma2(q1.y, w2, acc[1]);
                    acc[2] = ffma2(q1.x, w0, acc[2]);
                    acc[2] = ffma2(q1.y, w1, acc[2]);
                    acc[2] = ffma2(q2.x, w2, acc[2]);
                    acc[3] = ffma2(q1.y, w0, acc[3]);
                    acc[3] = ffma2(q2.x, w1, acc[3]);
                    acc[3] = ffma2(q2.y, w2, acc[3]);
                    acc[4] = ffma2(q2.x, w0, acc[4]);
                    acc[4] = ffma2(q2.y, w1, acc[4]);
                    acc[4] = ffma2(q3.x, w2, acc[4]);
                    acc[5] = ffma2(q2.y, w0, acc[5]);
                    acc[5] = ffma2(q3.x, w1, acc[5]);
                    acc[5] = ffma2(q3.y, w2, acc[5]);
                }
#pragma unroll 2
                for (int fp = 0; fp < 8; fp++) {
                    const ulonglong2* row =
                        (const ulonglong2*)(myxr + fp * 24 + 12 * half);
                    ulonglong2 p0 = row[0], p1 = row[1], p2 = row[2];
                    u64 w = wru[fp * 64 + c];
                    acc[0] = ffma2(p0.x, w, acc[0]);
                    acc[1] = ffma2(p0.y, w, acc[1]);
                    acc[2] = ffma2(p1.x, w, acc[2]);
                    acc[3] = ffma2(p1.y, w, acc[3]);
                    acc[4] = ffma2(p2.x, w, acc[4]);
                    acc[5] = ffma2(p2.y, w, acc[5]);
                }
#pragma unroll
                for (int tt = 0; tt < 6; tt++) {
                    int t = half * 6 + tt;
                    h[t] = fmaxf(hsum2(acc[tt]) + bb, 0.f);
                    myhs[t * 64 + c] = h[t];
                }
            }
        }
        __syncthreads();

        // ---- LN stats: each of the group's 2 warps reduces 6 t-rows ----
        {
#pragma unroll
            for (int r = 0; r < 6; r++) {
                int t = w01 * 6 + r;
                float v1 = myhs[t * 64 + lane];
                float v2 = myhs[t * 64 + 32 + lane];
                float s = v1 + v2;
                float sq = v1 * v1 + v2 * v2;
#pragma unroll
                for (int o = 16; o > 0; o >>= 1) {
                    s  += __shfl_xor_sync(0xffffffffu, s, o);
                    sq += __shfl_xor_sync(0xffffffffu, sq, o);
                }
                if (lane == 0) {
                    float mu = s * (1.0f / 64.0f);
                    float var = sq * (1.0f / 64.0f) - mu * mu;
                    mymu[t] = mu;
                    myrs[t] = rsqrtf(var + 1e-5f);
                }
            }
        }
        __syncthreads();

        // ---- normalize + write out (B,N,C,T), coalesced float4 ----
        // (no trailing barrier: next iteration's stage-0 writes only tx/xr,
        //  whose readers are already barrier-separated)
        {
            float ga = gma[c], be = bta[c];
            float o[12];
#pragma unroll
            for (int t = 0; t < 12; t++)
                o[t] = (h[t] - mymu[t]) * myrs[t] * ga + be;
            float* op = out + (((size_t)g * Nn + n) * 64 + c) * 12;
            float4* op4 = (float4*)op;
            op4[0] = make_float4(o[0], o[1], o[2],  o[3]);
            op4[1] = make_float4(o[4], o[5], o[6],  o[7]);
            op4[2] = make_float4(o[8], o[9], o[10], o[11]);
        }
    }
}

// ---------------- launcher ----------------
extern "C" void kernel_launch(void* const* d_in, const int* in_sizes, int n_in,
                              void* d_out, int out_size)
{
    const float* x     = (const float*)d_in[0];
    const int*   ei    = (const int*)d_in[1];
    const float* lam   = (const float*)d_in[2];
    const float* chebW = (const float*)d_in[3];
    const float* chebB = (const float*)d_in[4];
    const float* timeW = (const float*)d_in[5];
    const float* timeB = (const float*)d_in[6];
    const float* resW  = (const float*)d_in[7];
    const float* resB  = (const float*)d_in[8];
    const float* gma   = (const float*)d_in[9];
    const float* bta   = (const float*)d_in[10];
    float* out = (float*)d_out;

    k_zero<<<(Nn + 255) / 256, 256>>>();
    k_count<<<(Ee + 255) / 256, 256>>>(ei);
    k_scan<<<1, 1024>>>();
    k_fill<<<(Ee + 255) / 256, 256>>>(ei);
    k_transpose<<<Bb * Nn, 192>>>(x);
    k_lhat1<<<Nn, 192>>>(lam);
    k_lhat2<<<Nn, 192>>>(lam);

    cudaFuncSetAttribute(k_fused, cudaFuncAttributeMaxDynamicSharedMemorySize,
                         SMEM_FLOATS * 4);
    // persistent grid: 2 blocks per SM, weights staged once per block
    k_fused<<<296, 256, SMEM_FLOATS * 4>>>(x, chebW, chebB, timeW, timeB,
                                           resW, resB, gma, bta, out);
}

// round 4
// speedup vs baseline: 2.0135x; 1.1595x over previous
#include <cuda_runtime.h>

// Problem constants
#define Nn   10000
#define Bb   4
#define Ff   16
#define Tt   12
#define Ee   160000
#define Cc   64
#define ROW  768          // Bb*Tt*Ff floats per node
#define ROW4 192          // ROW/4 (float4)

typedef unsigned long long u64;

__device__ __forceinline__ u64 ffma2(u64 a, u64 b, u64 c) {
    u64 d;
    asm("fma.rn.f32x2 %0, %1, %2, %3;" : "=l"(d) : "l"(a), "l"(b), "l"(c));
    return d;
}
__device__ __forceinline__ float hsum2(u64 v) {
    float lo, hi;
    asm("mov.b64 {%0, %1}, %2;" : "=f"(lo), "=f"(hi) : "l"(v));
    return lo + hi;
}
#define GROUP_BAR(gid) asm volatile("bar.sync %0, 64;" :: "r"((gid) + 1) : "memory")

// ---------------- scratch (device globals; no allocation) ----------------
__device__ float g_Tx0[Nn * ROW];
__device__ float g_Tx1[Nn * ROW];
__device__ float g_Tx2[Nn * ROW];
__device__ float g_deg[Nn];
__device__ int   g_degin[Nn];
__device__ int   g_off[Nn + 1];
__device__ int   g_cur[Nn];
__device__ int   g_srcs[Ee];

// ---------------- graph preprocessing ----------------
__global__ void k_zero() {
    int i = blockIdx.x * blockDim.x + threadIdx.x;
    if (i < Nn) { g_deg[i] = 0.0f; g_degin[i] = 0; }
}

__global__ void k_count(const int* __restrict__ ei) {
    int e = blockIdx.x * blockDim.x + threadIdx.x;
    if (e < Ee) {
        atomicAdd(&g_deg[ei[e]], 1.0f);       // out-degree by row
        atomicAdd(&g_degin[ei[Ee + e]], 1);   // in-degree by col
    }
}

// single-block exclusive scan over g_degin -> g_off, g_cur
__global__ void k_scan() {
    __shared__ int part[1024];
    int t = threadIdx.x;
    const int CH = 10;                 // 1024*10 >= Nn
    int base = t * CH;
    int local[CH];
    int s = 0;
#pragma unroll
    for (int i = 0; i < CH; i++) {
        int idx = base + i;
        int v = (idx < Nn) ? g_degin[idx] : 0;
        local[i] = v; s += v;
    }
    part[t] = s;
    __syncthreads();
    for (int off = 1; off < 1024; off <<= 1) {
        int v = (t >= off) ? part[t - off] : 0;
        __syncthreads();
        part[t] += v;
        __syncthreads();
    }
    int pre = (t == 0) ? 0 : part[t - 1];
#pragma unroll
    for (int i = 0; i < CH; i++) {
        int idx = base + i;
        if (idx < Nn) { g_off[idx] = pre; g_cur[idx] = pre; pre += local[i]; }
    }
    if (t == 1023) g_off[Nn] = part[1023];
}

__global__ void k_fill(const int* __restrict__ ei) {
    int e = blockIdx.x * blockDim.x + threadIdx.x;
    if (e < Ee) {
        int c = ei[Ee + e];
        int p = atomicAdd(&g_cur[c], 1);
        g_srcs[p] = ei[e];
    }
}

// ---------------- transpose x (B,N,F,T) -> Tx0 (N,B,T,F) ----------------
__global__ void k_transpose(const float* __restrict__ x) {
    int bn = blockIdx.x;               // b*Nn + n
    int b = bn / Nn, n = bn - b * Nn;
    __shared__ float tile[ROW4];
    int tid = threadIdx.x;             // 0..191
    tile[tid] = x[bn * ROW4 + tid];    // (f*12 + t)
    __syncthreads();
    int t = tid >> 4, f = tid & 15;
    g_Tx0[n * ROW + b * ROW4 + tid] = tile[f * Tt + t];  // (t*16 + f)
}

// ---------------- Lhat via CSR gather ----------------
__global__ void k_lhat1(const float* __restrict__ lamp) {
    int n = blockIdx.x, j = threadIdx.x;     // j: float4 index 0..191
    const float4* u = (const float4*)g_Tx0;
    float4 acc = make_float4(0.f, 0.f, 0.f, 0.f);
    int e = g_off[n], e1 = g_off[n + 1];
    for (; e + 4 <= e1; e += 4) {
        int s0 = g_srcs[e], s1 = g_srcs[e + 1], s2 = g_srcs[e + 2], s3 = g_srcs[e + 3];
        float4 v0 = u[s0 * ROW4 + j], v1 = u[s1 * ROW4 + j];
        float4 v2 = u[s2 * ROW4 + j], v3 = u[s3 * ROW4 + j];
        acc.x += (v0.x + v1.x) + (v2.x + v3.x);
        acc.y += (v0.y + v1.y) + (v2.y + v3.y);
        acc.z += (v0.z + v1.z) + (v2.z + v3.z);
        acc.w += (v0.w + v1.w) + (v2.w + v3.w);
    }
    for (; e < e1; e++) {
        float4 v = u[g_srcs[e] * ROW4 + j];
        acc.x += v.x; acc.y += v.y; acc.z += v.z; acc.w += v.w;
    }
    float4 un = u[n * ROW4 + j];
    float c2 = 2.0f / lamp[0];
    float dn = g_deg[n];
    float4 r;
    r.x = c2 * (dn * un.x - acc.x) - un.x;
    r.y = c2 * (dn * un.y - acc.y) - un.y;
    r.z = c2 * (dn * un.z - acc.z) - un.z;
    r.w = c2 * (dn * un.w - acc.w) - un.w;
    ((float4*)g_Tx1)[n * ROW4 + j] = r;
}

__global__ void k_lhat2(const float* __restrict__ lamp) {
    int n = blockIdx.x, j = threadIdx.x;
    const float4* u = (const float4*)g_Tx1;
    float4 acc = make_float4(0.f, 0.f, 0.f, 0.f);
    int e = g_off[n], e1 = g_off[n + 1];
    for (; e + 4 <= e1; e += 4) {
        int s0 = g_srcs[e], s1 = g_srcs[e + 1], s2 = g_srcs[e + 2], s3 = g_srcs[e + 3];
        float4 v0 = u[s0 * ROW4 + j], v1 = u[s1 * ROW4 + j];
        float4 v2 = u[s2 * ROW4 + j], v3 = u[s3 * ROW4 + j];
        acc.x += (v0.x + v1.x) + (v2.x + v3.x);
        acc.y += (v0.y + v1.y) + (v2.y + v3.y);
        acc.z += (v0.z + v1.z) + (v2.z + v3.z);
        acc.w += (v0.w + v1.w) + (v2.w + v3.w);
    }
    for (; e < e1; e++) {
        float4 v = u[g_srcs[e] * ROW4 + j];
        acc.x += v.x; acc.y += v.y; acc.z += v.z; acc.w += v.w;
    }
    float4 un = u[n * ROW4 + j];
    float4 t0 = ((const float4*)g_Tx0)[n * ROW4 + j];
    float c2 = 2.0f / lamp[0];
    float dn = g_deg[n];
    float4 r;
    r.x = 2.0f * (c2 * (dn * un.x - acc.x) - un.x) - t0.x;
    r.y = 2.0f * (c2 * (dn * un.y - acc.y) - un.y) - t0.y;
    r.z = 2.0f * (c2 * (dn * un.z - acc.z) - un.z) - t0.z;
    r.w = 2.0f * (c2 * (dn * un.w - acc.w) - un.w) - t0.w;
    ((float4*)g_Tx2)[n * ROW4 + j] = r;
}

// ---------------- fused cheb-proj + temporal conv + residual + LN ----------------
// f32x2-packed, per-group NAMED barriers: the 4 independent 64-thread groups
// free-run against each other so FFMA phases of one group overlap LDS/global
// phases of another.
#define GB_BASE 16640
#define GB_STRIDE 2456
#define SMEM_FLOATS (GB_BASE + 4 * GB_STRIDE)   // 26464 floats = 105856 B

__global__ void __launch_bounds__(256, 2)
k_fused(const float* __restrict__ x,
        const float* __restrict__ chebW, const float* __restrict__ chebB,
        const float* __restrict__ timeW, const float* __restrict__ timeB,
        const float* __restrict__ resW,  const float* __restrict__ resB,
        const float* __restrict__ gamma, const float* __restrict__ beta,
        float* __restrict__ out)
{
    extern __shared__ float sm[];
    float* cb  = sm + 16384;
    float* trb = sm + 16448;
    float* gma = sm + 16512;
    float* bta = sm + 16576;

    const u64* wchu = (const u64*)(sm);          // [jp*64 + c]
    const u64* wtu  = (const u64*)(sm + 3072);   // [d*2048 + cip*64 + c]
    const u64* wru  = (const u64*)(sm + 15360);  // [fp*64 + c]

    int tid = threadIdx.x;

    // --- one-time weight staging (packed float2 over reduction pairs) ---
    for (int i = tid; i < 1536; i += 256) {          // cheb: jp(24), c(64)
        int jp = i >> 6, c = i & 63;
        sm[2 * i]     = chebW[(2 * jp) * 64 + c];
        sm[2 * i + 1] = chebW[(2 * jp + 1) * 64 + c];
    }
    for (int i = tid; i < 6144; i += 256) {          // time: d(3), cip(32), c(64)
        int d = i >> 11; int r = i & 2047;
        int cip = r >> 6; int c = r & 63;
        sm[3072 + 2 * i]     = timeW[c * 192 + (2 * cip) * 3 + d];
        sm[3072 + 2 * i + 1] = timeW[c * 192 + (2 * cip + 1) * 3 + d];
    }
    for (int i = tid; i < 512; i += 256) {           // res: fp(8), c(64)
        int fp = i >> 6, c = i & 63;
        sm[15360 + 2 * i]     = resW[c * 16 + 2 * fp];
        sm[15360 + 2 * i + 1] = resW[c * 16 + 2 * fp + 1];
    }
    if (tid < 64) {
        cb[tid]  = chebB[tid];
        trb[tid] = timeB[tid] + resB[tid];
        gma[tid] = gamma[tid];
        bta[tid] = beta[tid];
    }

    const int g = tid >> 6;        // group = batch b
    const int c = tid & 63;        // channel (also lane-in-group)
    const int lane = tid & 31;
    const int w01 = (tid >> 5) & 1;

    float* gbase  = sm + GB_BASE + g * GB_STRIDE;
    float* mytx   = gbase;              // 576: u64[jp(24)][t(12)]
    float* myspad = gbase + 576;        // 896: u64[cip(32)][tpos(14)]
    float* myxr   = gbase + 1472;       // 192: u64[fp(8)][t(12)]
    float* myhs   = gbase + 1664;       // 768: [t(12)][c(64)]
    float* mymu   = gbase + 2432;
    float* myrs   = gbase + 2444;

    // zero spad boundary slots (tpos 0 and 13) once; only [1..12] rewritten
    {
        float* sp = myspad + (c >> 1) * 28 + (c & 1);
        sp[0] = 0.f; sp[26] = 0.f;
    }
    __syncthreads();   // weights + boundary visible to all groups

    for (int q = blockIdx.x; q < Nn; q += gridDim.x) {
        const int n = q;

        // ---- Stage 0: group-local loads (coalesced global -> interleaved smem) ----
        {
            const float* srcs[3] = { g_Tx0, g_Tx1, g_Tx2 };
#pragma unroll
            for (int kk = 0; kk < 3; kk++) {
                const float* src = srcs[kk] + n * ROW + g * ROW4;
#pragma unroll
                for (int rep = 0; rep < 3; rep++) {
                    int rr = rep * 64 + c;          // 0..191 = t*16+f
                    int t = rr >> 4, f = rr & 15;
                    int j = kk * 16 + f;
                    mytx[(j >> 1) * 24 + t * 2 + (j & 1)] = src[rr];
                }
            }
            const float* xs = x + (g * Nn + n) * ROW4;
#pragma unroll
            for (int rep = 0; rep < 3; rep++) {
                int rr = rep * 64 + c;              // 0..191 = f*12+t
                int f = rr / 12, t = rr - f * 12;
                myxr[(f >> 1) * 24 + t * 2 + (f & 1)] = xs[rr];
            }
        }
        GROUP_BAR(g);

        // ---- Stage A: cheb projection (packed over j-pairs), relu -> spad ----
        {
            u64 acc[12];
#pragma unroll
            for (int t = 0; t < 12; t++) acc[t] = 0ull;
#pragma unroll 2
            for (int jp = 0; jp < 24; jp++) {
                const ulonglong2* row = (const ulonglong2*)(mytx + jp * 24);
                ulonglong2 p0 = row[0], p1 = row[1], p2 = row[2];
                ulonglong2 p3 = row[3], p4 = row[4], p5 = row[5];
                u64 w = wchu[jp * 64 + c];
                acc[0]  = ffma2(p0.x, w, acc[0]);  acc[1]  = ffma2(p0.y, w, acc[1]);
                acc[2]  = ffma2(p1.x, w, acc[2]);  acc[3]  = ffma2(p1.y, w, acc[3]);
                acc[4]  = ffma2(p2.x, w, acc[4]);  acc[5]  = ffma2(p2.y, w, acc[5]);
                acc[6]  = ffma2(p3.x, w, acc[6]);  acc[7]  = ffma2(p3.y, w, acc[7]);
                acc[8]  = ffma2(p4.x, w, acc[8]);  acc[9]  = ffma2(p4.y, w, acc[9]);
                acc[10] = ffma2(p5.x, w, acc[10]); acc[11] = ffma2(p5.y, w, acc[11]);
            }
            float bias = cb[c];
            float* sp = myspad + (c >> 1) * 28 + (c & 1);
#pragma unroll
            for (int t = 0; t < 12; t++)
                sp[(t + 1) * 2] = fmaxf(hsum2(acc[t]) + bias, 0.f);
        }
        GROUP_BAR(g);

        // ---- Stage B: temporal conv + residual in two 6-t half-passes ----
        float h[12];
        {
            float bb = trb[c];
#pragma unroll
            for (int half = 0; half < 2; half++) {
                u64 acc[6];
#pragma unroll
                for (int tt = 0; tt < 6; tt++) acc[tt] = 0ull;
#pragma unroll 1
                for (int cip = 0; cip < 32; cip++) {
                    const ulonglong2* row =
                        (const ulonglong2*)(myspad + cip * 28 + 12 * half);
                    ulonglong2 q0 = row[0], q1 = row[1], q2 = row[2], q3 = row[3];
                    u64 w0 = wtu[cip * 64 + c];
                    u64 w1 = wtu[2048 + cip * 64 + c];
                    u64 w2 = wtu[4096 + cip * 64 + c];
                    acc[0] = ffma2(q0.x, w0, acc[0]);
                    acc[0] = ffma2(q0.y, w1, acc[0]);
                    acc[0] = ffma2(q1.x, w2, acc[0]);
                    acc[1] = ffma2(q0.y, w0, acc[1]);
                    acc[1] = ffma2(q1.x, w1, acc[1]);
                    acc[1] = ffma2(q1.y, w2, acc[1]);
                    acc[2] = ffma2(q1.x, w0, acc[2]);
                    acc[2] = ffma2(q1.y, w1, acc[2]);
                    acc[2] = ffma2(q2.x, w2, acc[2]);
                    acc[3] = ffma2(q1.y, w0, acc[3]);
                    acc[3] = ffma2(q2.x, w1, acc[3]);
                    acc[3] = ffma2(q2.y, w2, acc[3]);
                    acc[4] = ffma2(q2.x, w0, acc[4]);
                    acc[4] = ffma2(q2.y, w1, acc[4]);
                    acc[4] = ffma2(q3.x, w2, acc[4]);
                    acc[5] = ffma2(q2.y, w0, acc[5]);
                    acc[5] = ffma2(q3.x, w1, acc[5]);
                    acc[5] = ffma2(q3.y, w2, acc[5]);
                }
#pragma unroll 2
                for (int fp = 0; fp < 8; fp++) {
                    const ulonglong2* row =
                        (const ulonglong2*)(myxr + fp * 24 + 12 * half);
                    ulonglong2 p0 = row[0], p1 = row[1], p2 = row[2];
                    u64 w = wru[fp * 64 + c];
                    acc[0] = ffma2(p0.x, w, acc[0]);
                    acc[1] = ffma2(p0.y, w, acc[1]);
                    acc[2] = ffma2(p1.x, w, acc[2]);
                    acc[3] = ffma2(p1.y, w, acc[3]);
                    acc[4] = ffma2(p2.x, w, acc[4]);
                    acc[5] = ffma2(p2.y, w, acc[5]);
                }
#pragma unroll
                for (int tt = 0; tt < 6; tt++) {
                    int t = half * 6 + tt;
                    h[t] = fmaxf(hsum2(acc[tt]) + bb, 0.f);
                    myhs[t * 64 + c] = h[t];
                }
            }
        }
        GROUP_BAR(g);

        // ---- LN stats: each of the group's 2 warps reduces 6 t-rows ----
        {
#pragma unroll
            for (int r = 0; r < 6; r++) {
                int t = w01 * 6 + r;
                float v1 = myhs[t * 64 + lane];
                float v2 = myhs[t * 64 + 32 + lane];
                float s = v1 + v2;
                float sq = v1 * v1 + v2 * v2;
#pragma unroll
                for (int o = 16; o > 0; o >>= 1) {
                    s  += __shfl_xor_sync(0xffffffffu, s, o);
                    sq += __shfl_xor_sync(0xffffffffu, sq, o);
                }
                if (lane == 0) {
                    float mu = s * (1.0f / 64.0f);
                    float var = sq * (1.0f / 64.0f) - mu * mu;
                    mymu[t] = mu;
                    myrs[t] = rsqrtf(var + 1e-5f);
                }
            }
        }
        GROUP_BAR(g);

        // ---- normalize + write out (B,N,C,T), coalesced float4 ----
        // (no trailing barrier: next stage-0 writes only tx/xr, whose last
        //  readers are behind the stage-A/B barriers above)
        {
            float ga = gma[c], be = bta[c];
            float o[12];
#pragma unroll
            for (int t = 0; t < 12; t++)
                o[t] = (h[t] - mymu[t]) * myrs[t] * ga + be;
            float* op = out + (((size_t)g * Nn + n) * 64 + c) * 12;
            float4* op4 = (float4*)op;
            op4[0] = make_float4(o[0], o[1], o[2],  o[3]);
            op4[1] = make_float4(o[4], o[5], o[6],  o[7]);
            op4[2] = make_float4(o[8], o[9], o[10], o[11]);
        }
    }
}

// ---------------- launcher ----------------
extern "C" void kernel_launch(void* const* d_in, const int* in_sizes, int n_in,
                              void* d_out, int out_size)
{
    const float* x     = (const float*)d_in[0];
    const int*   ei    = (const int*)d_in[1];
    const float* lam   = (const float*)d_in[2];
    const float* chebW = (const float*)d_in[3];
    const float* chebB = (const float*)d_in[4];
    const float* timeW = (const float*)d_in[5];
    const float* timeB = (const float*)d_in[6];
    const float* resW  = (const float*)d_in[7];
    const float* resB  = (const float*)d_in[8];
    const float* gma   = (const float*)d_in[9];
    const float* bta   = (const float*)d_in[10];
    float* out = (float*)d_out;

    k_zero<<<(Nn + 255) / 256, 256>>>();
    k_count<<<(Ee + 255) / 256, 256>>>(ei);
    k_scan<<<1, 1024>>>();
    k_fill<<<(Ee + 255) / 256, 256>>>(ei);
    k_transpose<<<Bb * Nn, 192>>>(x);
    k_lhat1<<<Nn, 192>>>(lam);
    k_lhat2<<<Nn, 192>>>(lam);

    cudaFuncSetAttribute(k_fused, cudaFuncAttributeMaxDynamicSharedMemorySize,
                         SMEM_FLOATS * 4);
    // persistent grid: 2 blocks per SM, weights staged once per block
    k_fused<<<296, 256, SMEM_FLOATS * 4>>>(x, chebW, chebB, timeW, timeB,
                                           resW, resB, gma, bta, out);
}